// round 6
// baseline (speedup 1.0000x reference)
#include <cuda_runtime.h>
#include <cstdint>

// LIF recurrence: v = alpha*v + beta*c; spike = (v >= 1); v = spike ? 0 : v.
// Sequential over T=2048, parallel over N=32768.
// Output: out[0 : T*N] = spikes, out[T*N : 2*T*N] = post-reset voltages.
//
// R2-R5 all plateau at DRAM~61% because warp-issued loads cap at ~55
// outstanding ops/warp => ~56KB/SM in flight, independent of scheme.
// R6: feed the current stream through the TMA/bulk engine (UBLKCP) into a
// 64-step smem ring with mbarrier full/empty pairs. Engine-tracked transfers
// bypass the warp scoreboard cap entirely.

#define T_STEPS 2048
#define N_NEUR  32768
#define BLOCK   256
#define GRID    (N_NEUR / BLOCK)    // 128 CTAs, <=1 per SM
#define NWARP   (BLOCK / 32)        // 8
#define GSTEPS  8                   // steps per ring slot
#define NSLOT   8                   // ring depth in slots (64 steps total)
#define NGROUP  (T_STEPS / GSTEPS)  // 256 groups
#define ROWB    (BLOCK * 4)         // 1024 bytes per step-row
#define SLOTB   (GSTEPS * ROWB)     // 8192 bytes per slot
#define DATAB   (NSLOT * SLOTB)     // 65536 bytes of ring data
#define SMEM_TOTAL (DATAB + 2 * NSLOT * 8)   // + full/empty mbarriers

__device__ __forceinline__ unsigned smem_u32(const void* p)
{
    return (unsigned)__cvta_generic_to_shared(p);
}

__device__ __forceinline__ void mbar_init(unsigned mbar, unsigned count)
{
    asm volatile("mbarrier.init.shared.b64 [%0], %1;" :: "r"(mbar), "r"(count) : "memory");
}
__device__ __forceinline__ void mbar_expect_tx(unsigned mbar, unsigned bytes)
{
    asm volatile("mbarrier.arrive.expect_tx.shared.b64 _, [%0], %1;"
                 :: "r"(mbar), "r"(bytes) : "memory");
}
__device__ __forceinline__ void mbar_arrive(unsigned mbar)
{
    asm volatile("mbarrier.arrive.shared.b64 _, [%0];" :: "r"(mbar) : "memory");
}
__device__ __forceinline__ void mbar_wait(unsigned mbar, unsigned parity)
{
    asm volatile(
        "{\n\t"
        ".reg .pred P;\n\t"
        "WAIT_%=: \n\t"
        "mbarrier.try_wait.parity.acquire.cta.shared::cta.b64 P, [%0], %1, 0x989680;\n\t"
        "@P bra.uni DONE_%=;\n\t"
        "bra.uni WAIT_%=;\n\t"
        "DONE_%=: \n\t"
        "}"
        :: "r"(mbar), "r"(parity) : "memory");
}
__device__ __forceinline__ void bulk_ld(unsigned sdst, const void* gsrc,
                                        unsigned bytes, unsigned mbar)
{
    asm volatile(
        "cp.async.bulk.shared::cta.global.mbarrier::complete_tx::bytes "
        "[%0], [%1], %2, [%3];"
        :: "r"(sdst), "l"(gsrc), "r"(bytes), "r"(mbar) : "memory");
}

__global__ void __launch_bounds__(BLOCK, 1)
lif_kernel(const float* __restrict__ cur,
           const float* __restrict__ v0,
           float* __restrict__ out)
{
    extern __shared__ char smem[];
    float*    sdata = (float*)smem;
    uint64_t* mbars = (uint64_t*)(smem + DATAB);   // [full0..full7, empty0..empty7]

    const int tid  = threadIdx.x;
    const int lane = tid & 31;
    const int n    = blockIdx.x * BLOCK + tid;

    const unsigned sdata_u = smem_u32(sdata);
    const unsigned full0   = smem_u32(mbars);
    const unsigned empty0  = smem_u32(mbars + NSLOT);

    // Reference f32 constants: alpha = f32(exp(-1/20)), beta = f32(1 - alpha)
    const float alpha = (float)0.9512294245007140;
    const float beta  = (float)(1.0 - 0.9512294245007140);

    float v = v0[n];

    // Per-CTA base of the current stream (1024 B rows, stride N floats).
    const char* gbase = (const char*)(cur + (size_t)blockIdx.x * BLOCK);

    float* sp = out + n;                                  // spikes
    float* vp = out + (size_t)T_STEPS * N_NEUR + n;       // voltages

    // ---- Init barriers ----
    if (tid == 0) {
#pragma unroll
        for (int s = 0; s < NSLOT; ++s) {
            mbar_init(full0  + 8u * s, 1);        // completed by expect_tx + tx bytes
            mbar_init(empty0 + 8u * s, NWARP);    // one arrive per warp
        }
        asm volatile("fence.proxy.async.shared::cta;" ::: "memory");
    }
    __syncthreads();

    // ---- Prime: fill all 8 slots (groups 0..7) ----
    if (tid == 0) {
#pragma unroll
        for (int g = 0; g < NSLOT; ++g) {
            const unsigned mb = full0 + 8u * g;
            mbar_expect_tx(mb, SLOTB);
#pragma unroll
            for (int i = 0; i < GSTEPS; ++i)
                bulk_ld(sdata_u + (unsigned)(g * SLOTB + i * ROWB),
                        gbase + (size_t)(g * GSTEPS + i) * N_NEUR * 4, ROWB, mb);
        }
    }

    // ---- Main loop: one 8-step group per iteration ----
    for (int g = 0; g < NGROUP; ++g) {
        const int slot = g & (NSLOT - 1);
        const unsigned parity = (unsigned)((g >> 3) & 1);

        mbar_wait(full0 + 8u * slot, parity);      // acquire: TMA data visible

        // Read this group's 8 currents, compute, store.
        float c[GSTEPS];
        const float* srow = sdata + slot * (GSTEPS * BLOCK) + tid;
#pragma unroll
        for (int i = 0; i < GSTEPS; ++i)
            c[i] = srow[i * BLOCK];

#pragma unroll
        for (int i = 0; i < GSTEPS; ++i) {
            // explicitly unfused to match reference rounding
            v = __fadd_rn(__fmul_rn(alpha, v), __fmul_rn(beta, c[i]));
            const bool fire = (v >= 1.0f);
            const float s = fire ? 1.0f : 0.0f;
            v = fire ? 0.0f : v;
            *sp = s;
            *vp = v;
            sp += N_NEUR;
            vp += N_NEUR;
        }

        __syncwarp();
        if (lane == 0)
            mbar_arrive(empty0 + 8u * slot);       // per-warp arrival

        // Producer: refill this slot for group g+NSLOT.
        if (tid == 0 && g + NSLOT < NGROUP) {
            mbar_wait(empty0 + 8u * slot, parity); // all 8 warps done with slot
            const unsigned mb = full0 + 8u * slot;
            mbar_expect_tx(mb, SLOTB);
            const int gf = g + NSLOT;
#pragma unroll
            for (int i = 0; i < GSTEPS; ++i)
                bulk_ld(sdata_u + (unsigned)(slot * SLOTB + i * ROWB),
                        gbase + (size_t)(gf * GSTEPS + i) * N_NEUR * 4, ROWB, mb);
        }
    }
}

extern "C" void kernel_launch(void* const* d_in, const int* in_sizes, int n_in,
                              void* d_out, int out_size)
{
    const float* currents = (const float*)d_in[0];   // (T, N) float32
    const float* v0       = (const float*)d_in[1];   // (N,)  float32
    float* out            = (float*)d_out;           // 2*T*N float32

    static int configured = 0;
    if (!configured) {
        cudaFuncSetAttribute(lif_kernel,
                             cudaFuncAttributeMaxDynamicSharedMemorySize,
                             SMEM_TOTAL);
        configured = 1;
    }
    lif_kernel<<<GRID, BLOCK, SMEM_TOTAL>>>(currents, v0, out);
}

// round 7
// speedup vs baseline: 1.4141x; 1.4141x over previous
#include <cuda_runtime.h>

// LIF recurrence: v = alpha*v + beta*c; spike = (v >= 1); v = spike ? 0 : v.
// Sequential over T=2048, parallel over N=32768.
// Output: out[0 : T*N] = spikes, out[T*N : 2*T*N] = voltages (post-reset).
//
// R4/R5 falsified the latency-coverage model (in-flight bytes don't move
// DRAM% past ~62). R6 showed the TMA engine is worse for <=1KB transfers.
// R7 attacks memory-op rate + DRAM bus efficiency:
//   - float2 per thread: halves all LDGSTS/LDS/STG op counts
//   - 8-step groups computed in registers, stores flushed stream-by-stream
//     (8 spike rows, then 8 voltage rows) => 2KB same-direction write runs
//   - proven cp.async smem ring (32 steps, 4 commit groups) for reads

#define T_STEPS 2048
#define N_NEUR  32768
#define BLOCK   128
#define VEC     2                   // neurons per thread
#define CHUNK   (BLOCK * VEC)       // 256 neurons per CTA
#define GRID    (N_NEUR / CHUNK)    // 128 CTAs, 1 per SM
#define STAGES  32                  // smem ring depth (steps)
#define GRP     8                   // steps per commit group
#define NGRP    (STAGES / GRP)      // 4 groups in flight

__device__ __forceinline__ void cp_async8(unsigned saddr, const float2* gptr)
{
    asm volatile("cp.async.ca.shared.global [%0], [%1], 8;"
                 :: "r"(saddr), "l"(gptr));
}
__device__ __forceinline__ void cp_commit()
{
    asm volatile("cp.async.commit_group;");
}
__device__ __forceinline__ void cp_wait_allow()
{
    asm volatile("cp.async.wait_group %0;" :: "n"(NGRP - 1));
}

__global__ void __launch_bounds__(BLOCK, 1)
lif_kernel(const float* __restrict__ cur,
           const float* __restrict__ v0,
           float* __restrict__ out)
{
    __shared__ float2 sbuf[STAGES * BLOCK];   // 32 KB

    const int tid  = threadIdx.x;
    const int base = blockIdx.x * CHUNK + tid * VEC;   // first of this thread's 2 neurons

    // Reference f32 constants: alpha = f32(exp(-1/20)), beta = f32(1 - alpha)
    const float alpha = (float)0.9512294245007140;
    const float beta  = (float)(1.0 - 0.9512294245007140);

    float2 v = *(const float2*)(v0 + base);

    const float2* cp = (const float2*)(cur + base);        // row stride N_NEUR/2 float2
    float2* sp = (float2*)(out + base);                    // spikes
    float2* vp = (float2*)(out + (size_t)T_STEPS * N_NEUR + base);  // voltages

    const unsigned sbase =
        (unsigned)__cvta_generic_to_shared(sbuf) + (unsigned)tid * 8u;

    // ---- Prime: issue all STAGES stages as NGRP commit groups ----
#pragma unroll
    for (int g = 0; g < NGRP; ++g) {
#pragma unroll
        for (int i = 0; i < GRP; ++i) {
            const int s = g * GRP + i;
            cp_async8(sbase + (unsigned)(s * BLOCK) * 8u,
                      cp + (size_t)s * (N_NEUR / VEC));
        }
        cp_commit();
    }
    cp += (size_t)STAGES * (N_NEUR / VEC);

    // ---- Main loop: one 8-step group per iteration ----
    for (int t = 0; t < T_STEPS; t += GRP) {
        cp_wait_allow();                       // oldest group (steps t..t+7) ready

        const int slot = (t / GRP) & (NGRP - 1);

        // Read this group's 8 currents from smem...
        float2 c[GRP];
#pragma unroll
        for (int i = 0; i < GRP; ++i)
            c[i] = sbuf[(slot * GRP + i) * BLOCK + tid];

        // ...then reuse the slot for steps t+STAGES..t+STAGES+7.
        if (t + STAGES < T_STEPS) {
#pragma unroll
            for (int i = 0; i < GRP; ++i)
                cp_async8(sbase + (unsigned)((slot * GRP + i) * BLOCK) * 8u,
                          cp + (size_t)i * (N_NEUR / VEC));
            cp += (size_t)GRP * (N_NEUR / VEC);
        }
        cp_commit();                           // empty group near the tail is fine

        // Compute all 8 steps into registers (no stores yet).
        float2 sv[GRP];   // spikes
        float2 vv[GRP];   // post-reset voltages
#pragma unroll
        for (int i = 0; i < GRP; ++i) {
            // explicitly unfused to match reference rounding
            v.x = __fadd_rn(__fmul_rn(alpha, v.x), __fmul_rn(beta, c[i].x));
            v.y = __fadd_rn(__fmul_rn(alpha, v.y), __fmul_rn(beta, c[i].y));
            const bool fx = (v.x >= 1.0f);
            const bool fy = (v.y >= 1.0f);
            sv[i].x = fx ? 1.0f : 0.0f;
            sv[i].y = fy ? 1.0f : 0.0f;
            v.x = fx ? 0.0f : v.x;
            v.y = fy ? 0.0f : v.y;
            vv[i] = v;
        }

        // Flush stream-by-stream: 8 spike rows, then 8 voltage rows.
#pragma unroll
        for (int i = 0; i < GRP; ++i)
            sp[(size_t)i * (N_NEUR / VEC)] = sv[i];
        sp += (size_t)GRP * (N_NEUR / VEC);

#pragma unroll
        for (int i = 0; i < GRP; ++i)
            vp[(size_t)i * (N_NEUR / VEC)] = vv[i];
        vp += (size_t)GRP * (N_NEUR / VEC);
    }
}

extern "C" void kernel_launch(void* const* d_in, const int* in_sizes, int n_in,
                              void* d_out, int out_size)
{
    const float* currents = (const float*)d_in[0];   // (T, N) float32
    const float* v0       = (const float*)d_in[1];   // (N,)  float32
    float* out            = (float*)d_out;           // 2*T*N float32

    lif_kernel<<<GRID, BLOCK>>>(currents, v0, out);
}